// round 7
// baseline (speedup 1.0000x reference)
#include <cuda_runtime.h>

#define B_TOT   16384
#define TM      16
#define NTHR    768
#define NSTEPS_ 10

typedef unsigned long long u64;

__device__ __forceinline__ u64 pk2(float lo, float hi) {
    u64 r; asm("mov.b64 %0,{%1,%2};" : "=l"(r) : "f"(lo), "f"(hi)); return r;
}
__device__ __forceinline__ float2 upk2(u64 v) {
    float2 f; asm("mov.b64 {%0,%1},%2;" : "=f"(f.x), "=f"(f.y) : "l"(v)); return f;
}
__device__ __forceinline__ void fma2(u64& d, u64 a, u64 b) {
    asm("fma.rn.f32x2 %0,%1,%2,%0;" : "+l"(d) : "l"(a), "l"(b));
}
__device__ __forceinline__ void add2(u64& d, u64 a) {
    asm("add.rn.f32x2 %0,%0,%1;" : "+l"(d) : "l"(a));
}

// Shared layout (floats):
//   [0,36864)      W2s   192x192
//   [36864,43776)  shA   192x36 (aliased: hS 256x16, a2t 16x196)
//   [43776,46848)  shW1a 16x192
//   [46848,49920)  shW3t 16x192
//   [49920,49936)  shB3  16
//   [49936,50512)  shYE  16x36
//   [50512,51328)  shFJ3 3x(16x17)
//   [51328,52096)  shFB  3x256
//   [52096,52352)  shY   16x16
//   [52352,52368)  shTR  16
//   [52368,52464)  shTW  24x4 warp trace partials
#define SMEM_FLOATS 52464

__global__ __launch_bounds__(NTHR, 1)
void ConditionalCNF_27590869910221_kernel(
    const float* __restrict__ theta, const float* __restrict__ hg,
    const float* __restrict__ eps,   const float* __restrict__ W1,
    const float* __restrict__ b1,    const float* __restrict__ W2,
    const float* __restrict__ b2,    const float* __restrict__ W3,
    const float* __restrict__ b3,    float* __restrict__ out)
{
    extern __shared__ float sm[];
    float* shW2  = sm;
    float* shA   = sm + 36864;
    float* shW1a = sm + 43776;
    float* shW3t = sm + 46848;
    float* shB3  = sm + 49920;
    float* shYE  = sm + 49936;
    float* shFJ3 = sm + 50512;
    float* shFB  = sm + 51328;
    float* shY   = sm + 52096;
    float* shTR  = sm + 52352;
    float* shTW  = sm + 52368;

    const int tid = threadIdx.x;
    const int u = tid % 192;         // column index (one col per thread)
    const int g = tid / 192;         // sample quarter (0..3)
    const int wid = tid >> 5;        // warp id (uniform g per warp: 6 warps/group)
    const int lane = tid & 31;
    const int j0 = u;
    const int sb = 4 * g;            // sample base within tile
    const int s0 = blockIdx.x * TM;
    const float dtf = -0.1f;

    // per-thread constants (register-resident)
    const float w1tReg = W1[272 * 192 + j0];
    const float b2Reg  = b2[j0];

    // ---------------- phase 0: stage weights / state ----------------
    {
        const float4* W2g4 = (const float4*)W2;
        float4* shW24 = (float4*)shW2;
        for (int i = tid; i < 36864 / 4; i += NTHR) shW24[i] = W2g4[i];
        for (int i = tid; i < 3072; i += NTHR) shW1a[i] = W1[i];           // rows 0..15
        for (int i = tid; i < 3072; i += NTHR) {                           // W3 transpose
            int k = i >> 4, dd = i & 15;
            shW3t[dd * 192 + k] = W3[i];
        }
        if (tid < 16) { shB3[tid] = b3[tid]; shTR[tid] = 0.f; }
        for (int i = tid; i < 256; i += NTHR) shY[i] = theta[s0 * 16 + i];
        // h tile into shA as hS[c][s], row stride 16
        const float4* hg4 = (const float4*)hg;
        for (int i = tid; i < 1024; i += NTHR) {
            float4 v = hg4[s0 * 64 + i];
            int s = i >> 6, c = (i & 63) * 4;
            shA[(c + 0) * 16 + s] = v.x; shA[(c + 1) * 16 + s] = v.y;
            shA[(c + 2) * 16 + s] = v.z; shA[(c + 3) * 16 + s] = v.w;
        }
    }
    __syncthreads();

    // ---------------- hc = b1 + h @ W1[16:272,:]  (register resident) ----------------
    u64 hcReg[2];
    {
        float bj = b1[j0];
        u64 acc0 = pk2(bj, bj), acc1 = acc0;
        const float* hrow = shA + sb;
        #pragma unroll 4
        for (int k = 0; k < 256; k++) {
            float w = W1[(16 + k) * 192 + j0];                             // L2-resident
            u64 w0 = pk2(w, w);
            ulonglong2 A0 = *(const ulonglong2*)(hrow + k * 16);
            fma2(acc0, A0.x, w0); fma2(acc1, A0.y, w0);
        }
        hcReg[0] = acc0; hcReg[1] = acc1;
    }
    __syncthreads();

    const float kSQ = 0.70710678118654752f;    // 1/sqrt(2)
    const float kPDF = 0.3989422804014327f;    // 1/sqrt(2*pi)

    u64 aA[2], aD[2], aW[2];

    // eps prefetch: each of first 256 threads owns one (s,d) slot of the tile
    float epsReg = 0.f;
    const int es = tid >> 4, ed = tid & 15;
    if (tid < 256) epsReg = eps[((0 * B_TOT) + s0 + es) * 16 + ed];

    for (int step = 0; step < NSTEPS_; step++) {
        float t0 = 1.0f + dtf * (float)step;
        for (int st = 0; st < 4; st++) {
            int idx = step * 4 + st;
            float tc = t0 + dtf * (st == 0 ? 0.f : st == 1 ? (1.f / 3.f)
                                 : st == 2 ? (2.f / 3.f) : 1.f);

            // ---- phase A: stage y + eps into shYE (eps from prefetch reg) ----
            if (tid < 256) {
                int i = tid;
                int s = es, d = ed;
                shYE[d * 36 + 16 + s] = epsReg;
                float yb = shY[i];
                float yc;
                if      (st == 0) yc = yb;
                else if (st == 1) yc = yb + (dtf * (1.f / 3.f)) * shFB[i];
                else if (st == 2) yc = yb + dtf * (shFB[256 + i] - (1.f / 3.f) * shFB[i]);
                else              yc = yb + dtf * (shFB[i] - shFB[256 + i] + shFB[512 + i]);
                shYE[d * 36 + s] = yc;
                int nxt = idx + 1; if (nxt > 39) nxt = 39;
                epsReg = eps[((nxt * B_TOT) + s0 + s) * 16 + d];           // prefetch next stage
            }
            __syncthreads();

            // ---- layer 1: z1 = hc + t*W1t + y@W1a ; dz1 = e@W1a ; we = W3.e ----
            {
                float tw = tc * w1tReg;
                u64 twp = pk2(tw, tw);
                aA[0] = hcReg[0]; aA[1] = hcReg[1];
                add2(aA[0], twp); add2(aA[1], twp);
                aD[0] = aD[1] = 0ull;
                aW[0] = aW[1] = 0ull;
            }
            #pragma unroll
            for (int k = 0; k < 16; k++) {
                const float* ar = shYE + k * 36 + sb;
                ulonglong2 A0 = *(const ulonglong2*)ar;
                ulonglong2 E0 = *(const ulonglong2*)(ar + 16);
                float w  = shW1a[k * 192 + j0];
                float w3 = shW3t[k * 192 + j0];
                u64 w0 = pk2(w, w), v0 = pk2(w3, w3);
                fma2(aA[0], A0.x, w0); fma2(aA[1], A0.y, w0);
                fma2(aD[0], E0.x, w0); fma2(aD[1], E0.y, w0);
                fma2(aW[0], E0.x, v0); fma2(aW[1], E0.y, v0);
            }

            // GELU layer1 + store a1/d1 rows (1 col x 4 samples)
            {
                float va[4], vd[4];
                #pragma unroll
                for (int p = 0; p < 2; p++) {
                    float2 z  = upk2(aA[p]);
                    float2 dz = upk2(aD[p]);
                    float c0 = 0.5f * (1.f + erff(z.x * kSQ));
                    float c1 = 0.5f * (1.f + erff(z.y * kSQ));
                    va[2 * p]     = z.x * c0;
                    va[2 * p + 1] = z.y * c1;
                    float g0 = c0 + z.x * kPDF * __expf(-0.5f * z.x * z.x);
                    float g1 = c1 + z.y * kPDF * __expf(-0.5f * z.y * z.y);
                    vd[2 * p]     = g0 * dz.x;
                    vd[2 * p + 1] = g1 * dz.y;
                }
                float* row = shA + j0 * 36 + sb;
                *(float4*)(row)      = make_float4(va[0], va[1], va[2], va[3]);
                *(float4*)(row + 16) = make_float4(vd[0], vd[1], vd[2], vd[3]);
            }
            __syncthreads();

            // ---- layer 2: z2 = a1@W2 + b2 ; dz2 = d1@W2 ----
            {
                u64 bp = pk2(b2Reg, b2Reg);
                aA[0] = aA[1] = bp;
                aD[0] = aD[1] = 0ull;
            }
            #pragma unroll 8
            for (int k = 0; k < 192; k++) {
                const float* ar = shA + k * 36 + sb;
                ulonglong2 A0 = *(const ulonglong2*)ar;
                ulonglong2 E0 = *(const ulonglong2*)(ar + 16);
                float w = shW2[k * 192 + j0];
                u64 w0 = pk2(w, w);
                fma2(aA[0], A0.x, w0); fma2(aA[1], A0.y, w0);
                fma2(aD[0], E0.x, w0); fma2(aD[1], E0.y, w0);
            }
            __syncthreads();   // all reads of a1d1 done; shA reused as a2t

            // GELU layer2: store a2 transposed; trace partial from d2 in regs
            float tp[4];
            #pragma unroll
            for (int p = 0; p < 2; p++) {
                float2 z  = upk2(aA[p]);
                float2 dz = upk2(aD[p]);
                float c0 = 0.5f * (1.f + erff(z.x * kSQ));
                float c1 = 0.5f * (1.f + erff(z.y * kSQ));
                float a0 = z.x * c0, a1v = z.y * c1;
                float g0 = c0 + z.x * kPDF * __expf(-0.5f * z.x * z.x);
                float g1 = c1 + z.y * kPDF * __expf(-0.5f * z.y * z.y);
                float d0 = g0 * dz.x, d1v = g1 * dz.y;
                int ca = sb + 2 * p;
                shA[(ca)     * 196 + j0] = a0;
                shA[(ca + 1) * 196 + j0] = a1v;
                float2 wv = upk2(aW[p]);
                tp[2 * p]     = d0  * wv.x;      // d2 . (W3 e)
                tp[2 * p + 1] = d1v * wv.y;
            }
            // warp butterfly reduce the 4 sample-partials (warp uniform in g)
            #pragma unroll
            for (int off = 16; off > 0; off >>= 1) {
                #pragma unroll
                for (int i = 0; i < 4; i++)
                    tp[i] += __shfl_xor_sync(0xFFFFFFFFu, tp[i], off);
            }
            if (lane == 0) {
                #pragma unroll
                for (int i = 0; i < 4; i++) shTW[wid * 4 + i] = tp[i];
            }
            __syncthreads();

            // ---- layer 3 (a-path only): f = a2 @ W3, 3-way K-split over 768 thr ----
            {
                int o = tid & 255, third = tid >> 8;       // 3 x 256 tasks
                int s = o & 15, dd = o >> 4;
                const float* ap = shA + s * 196 + third * 64;
                const float* wp = shW3t + dd * 192 + third * 64;
                float acc = 0.f;
                #pragma unroll 8
                for (int k = 0; k < 64; k += 4) {
                    float4 av = *(const float4*)(ap + k);
                    float4 wv = *(const float4*)(wp + k);
                    acc += av.x * wv.x + av.y * wv.y + av.z * wv.z + av.w * wv.w;
                }
                shFJ3[third * 272 + s * 17 + dd] = acc;
            }
            __syncthreads();

            // ---- epilogue: f store / RK4 combine / trace accumulate ----
            float wst = (st == 1 || st == 2) ? 3.f : 1.f;
            if (tid < 256) {
                int i = tid;
                int s = es, d = ed;
                float f = shFJ3[s * 17 + d] + shFJ3[272 + s * 17 + d]
                        + shFJ3[544 + s * 17 + d] + shB3[d];
                if (st < 3) shFB[st * 256 + i] = f;
                else shY[i] += dtf * 0.125f *
                     (shFB[i] + 3.f * (shFB[256 + i] + shFB[512 + i]) + f);
            }
            if (tid < 16) {
                int s = tid;
                int gq = s >> 2, si = s & 3;
                float tr = 0.f;
                #pragma unroll
                for (int w = 0; w < 6; w++)
                    tr += shTW[(6 * gq + w) * 4 + si];
                shTR[s] += wst * tr;
            }
            __syncthreads();
        }
    }

    // logp = -0.5*||z0||^2 - 8*log(2pi) - dlogp ;  dlogp = -dt/8 * sum(w*tr)
    if (tid < 16) {
        int s = tid;
        float ss = 0.f;
        #pragma unroll
        for (int d = 0; d < 16; d++) { float v = shY[s * 16 + d]; ss += v * v; }
        out[s0 + s] = -0.5f * ss - 14.703016531274763f + dtf * 0.125f * shTR[s];
    }
}

extern "C" void kernel_launch(void* const* d_in, const int* in_sizes, int n_in,
                              void* d_out, int out_size) {
    const float* theta = (const float*)d_in[0];
    const float* hg    = (const float*)d_in[1];
    const float* eps   = (const float*)d_in[2];
    const float* W1    = (const float*)d_in[3];
    const float* b1    = (const float*)d_in[4];
    const float* W2    = (const float*)d_in[5];
    const float* b2    = (const float*)d_in[6];
    const float* W3    = (const float*)d_in[7];
    const float* b3    = (const float*)d_in[8];
    float* out = (float*)d_out;

    cudaFuncSetAttribute(ConditionalCNF_27590869910221_kernel,
                         cudaFuncAttributeMaxDynamicSharedMemorySize,
                         SMEM_FLOATS * (int)sizeof(float));
    ConditionalCNF_27590869910221_kernel<<<B_TOT / TM, NTHR,
                                           SMEM_FLOATS * sizeof(float)>>>(
        theta, hg, eps, W1, b1, W2, b2, W3, b3, out);
}